// round 2
// baseline (speedup 1.0000x reference)
#include <cuda_runtime.h>
#include <math.h>

#define NNODES_MAX 100000
#define NEDGES_MAX 1600000
#define IN_DIM 128
#define HID 64
#define KTOT 320   // IN_DIM + 3*HID
#define NCOLS 256  // 4 gates * HID

// ---------------- scratch (static device globals; no allocation) ----------------
__device__ __align__(16) float g_deg [NNODES_MAX];
__device__ __align__(16) float g_lapw[NEDGES_MAX];
__device__ __align__(16) float g_Tx1 [NNODES_MAX * HID];
__device__ __align__(16) float g_agg2[NNODES_MAX * HID];
__device__ __align__(16) float g_Wp  [KTOT * NCOLS];
__device__ __align__(16) float g_biasp[NCOLS];

// ---------------- helpers ----------------
__device__ __forceinline__ float sigf(float v) { return 1.0f / (1.0f + expf(-v)); }

__device__ __forceinline__ unsigned long long ffma2(unsigned long long a,
                                                    unsigned long long b,
                                                    unsigned long long c) {
    unsigned long long d;
    asm("fma.rn.f32x2 %0, %1, %2, %3;" : "=l"(d) : "l"(a), "l"(b), "l"(c));
    return d;
}
__device__ __forceinline__ float2 u2f(unsigned long long u) {
    float2 f; asm("mov.b64 {%0,%1}, %2;" : "=f"(f.x), "=f"(f.y) : "l"(u)); return f;
}

// ---------------- kernel 1: degree (segment_sum of w over src, self-loops removed) ----------------
__global__ void k_deg(const int* __restrict__ src, const int* __restrict__ dst,
                      const float* __restrict__ ew, int E) {
    int e = blockIdx.x * blockDim.x + threadIdx.x;
    if (e >= E) return;
    int s = src[e];
    float w = (s == dst[e]) ? 0.0f : ew[e];
    if (w != 0.0f) atomicAdd(&g_deg[s], w);
}

// ---------------- kernel 2: lap_w = -(dinv[src] * w * dinv[dst]) (lambda_max=2 -> scale 1) ----------------
__global__ void k_lapw(const int* __restrict__ src, const int* __restrict__ dst,
                       const float* __restrict__ ew, int E) {
    int e = blockIdx.x * blockDim.x + threadIdx.x;
    if (e >= E) return;
    int s = src[e], d = dst[e];
    float w  = (s == d) ? 0.0f : ew[e];
    float ds = g_deg[s], dd = g_deg[d];
    float is = (ds > 0.0f) ? rsqrtf(ds) : 0.0f;
    float id = (dd > 0.0f) ? rsqrtf(dd) : 0.0f;
    g_lapw[e] = -is * w * id;
}

// ---------------- kernel 3: pack big weight matrix [320][256] + fused bias ----------------
__global__ void k_pack(const float* __restrict__ Wx, const float* __restrict__ bg,
                       const float* __restrict__ theta, const float* __restrict__ convb) {
    int idx = blockIdx.x * blockDim.x + threadIdx.x;
    if (idx >= KTOT * NCOLS) return;
    int k = idx / NCOLS, j = idx % NCOLS;
    int g = j >> 6, o = j & 63;
    float v;
    if (k < IN_DIM) {
        v = Wx[(g * IN_DIM + k) * HID + o];
    } else {
        int kk = k - IN_DIM;
        int cheb = kk / HID, r = kk % HID;
        v = theta[((g * 3 + cheb) * HID + r) * HID + o];
    }
    g_Wp[idx] = v;
    if (idx < NCOLS) g_biasp[idx] = bg[idx] + convb[idx];
}

// ---------------- kernel 4: scatter  zout[dst] += lap_w * zin[src]  (64-wide rows, v4 red) ----------------
__global__ void k_scatter(const int* __restrict__ src, const int* __restrict__ dst,
                          const float* __restrict__ lapw,
                          const float4* __restrict__ zin, float* __restrict__ zout, int E) {
    long idx = (long)blockIdx.x * blockDim.x + threadIdx.x;
    int e = (int)(idx >> 4);
    if (e >= E) return;
    int c = (int)(idx & 15);
    float lw = lapw[e];
    if (lw == 0.0f) return;
    int s = src[e], d = dst[e];
    float4 v = zin[s * 16 + c];
    float* p = zout + ((long)d * 64 + c * 4);
    asm volatile("red.global.add.v4.f32 [%0], {%1,%2,%3,%4};"
                 :: "l"(p), "f"(lw * v.x), "f"(lw * v.y), "f"(lw * v.z), "f"(lw * v.w)
                 : "memory");
}

// ---------------- kernel 5: fused GEMM (320->256) + LSTM gates + relu(h0)@Wl + bl ----------------
// CTA: 64 nodes. Threads 256: p = tid&31 -> hid pair o=2p, ty = tid>>5 -> node stripe.
// Thread tile: 8 nodes x (4 gates x hid-pair) = 64 scalar accs as 32 packed f32x2.
#define NPB 64
#define KC  16
__global__ __launch_bounds__(256) void k_fused(
    const float* __restrict__ x, const float* __restrict__ h,
    const float* __restrict__ c, const float* __restrict__ Wl,
    const float* __restrict__ bl, float* __restrict__ out, int N) {

    __shared__ __align__(16) float sm[8192];   // 32KB, phase-unioned
    // phase1: Xs = sm[0..2048)   (KC x 128, node values DUPLICATED for f32x2)
    //         Ws = sm[2048..6144) (KC x 256)
    // phase2: Hs = sm[0..4096)   (64 x 64 relu(h0))
    //         Wls= sm[4096..8192) (64 x 64)

    const int tid = threadIdx.x;
    const int p  = tid & 31;
    const int ty = tid >> 5;
    const int nb = blockIdx.x * NPB;

    unsigned long long acc[8][4];
    {
        unsigned long long bini[4];
        #pragma unroll
        for (int g = 0; g < 4; ++g)
            bini[g] = *reinterpret_cast<const unsigned long long*>(&g_biasp[g * 64 + 2 * p]);
        #pragma unroll
        for (int i = 0; i < 8; ++i)
            #pragma unroll
            for (int g = 0; g < 4; ++g) acc[i][g] = bini[g];
    }

    for (int kc = 0; kc < KTOT / KC; ++kc) {
        const int k0 = kc * KC;
        __syncthreads();
        // ---- load X tile (64 nodes x 16 feats, duplicated) ----
        {
            const float* sp; int ld, col; bool tx2 = false;
            if (k0 < IN_DIM)                { sp = x;      ld = IN_DIM; col = k0; }
            else if (k0 < IN_DIM + HID)     { sp = h;      ld = HID;    col = k0 - IN_DIM; }
            else if (k0 < IN_DIM + 2 * HID) { sp = g_Tx1;  ld = HID;    col = k0 - IN_DIM - HID; }
            else                            { sp = g_agg2; ld = HID;    col = k0 - IN_DIM - 2 * HID; tx2 = true; }
            #pragma unroll
            for (int r = 0; r < 4; ++r) {
                int idx = tid + r * 256;
                int n = idx >> 4, cc = idx & 15;
                int gn = nb + n;
                float v = 0.0f;
                if (gn < N) {
                    v = sp[gn * ld + col + cc];
                    if (tx2) v = 2.0f * v - h[gn * HID + col + cc];
                }
                sm[cc * 128 + 2 * n]     = v;
                sm[cc * 128 + 2 * n + 1] = v;
            }
            const float4* wp4 = reinterpret_cast<const float4*>(g_Wp + k0 * NCOLS);
            float4* ws4 = reinterpret_cast<float4*>(sm + 2048);
            #pragma unroll
            for (int r = 0; r < 4; ++r) ws4[tid + r * 256] = wp4[tid + r * 256];
        }
        __syncthreads();
        // ---- f32x2 FMA inner loop ----
        #pragma unroll
        for (int kk = 0; kk < KC; ++kk) {
            const unsigned long long* xr =
                reinterpret_cast<const unsigned long long*>(sm + kk * 128);
            const unsigned long long* wr =
                reinterpret_cast<const unsigned long long*>(sm + 2048 + kk * 256);
            unsigned long long a[8], b[4];
            #pragma unroll
            for (int i = 0; i < 8; ++i) a[i] = xr[ty + 8 * i];
            #pragma unroll
            for (int g = 0; g < 4; ++g) b[g] = wr[g * 32 + p];
            #pragma unroll
            for (int i = 0; i < 8; ++i)
                #pragma unroll
                for (int g = 0; g < 4; ++g) acc[i][g] = ffma2(a[i], b[g], acc[i][g]);
        }
    }

    __syncthreads();  // phase1 smem dead -> reuse for Hs/Wls

    // ---- gates + write h0/c0, stage relu(h0) ----
    #pragma unroll
    for (int i = 0; i < 8; ++i) {
        int nl = ty + 8 * i;
        int n = nb + nl;
        float2 pi = u2f(acc[i][0]);
        float2 pf = u2f(acc[i][1]);
        float2 pt = u2f(acc[i][2]);
        float2 po = u2f(acc[i][3]);
        float r0 = 0.0f, r1 = 0.0f;
        if (n < N) {
            float2 cold = *reinterpret_cast<const float2*>(c + (long)n * HID + 2 * p);
            float ig0 = sigf(pi.x), ig1 = sigf(pi.y);
            float fg0 = sigf(pf.x), fg1 = sigf(pf.y);
            float tg0 = tanhf(pt.x), tg1 = tanhf(pt.y);
            float og0 = sigf(po.x), og1 = sigf(po.y);
            float c00 = fg0 * cold.x + ig0 * tg0;
            float c01 = fg1 * cold.y + ig1 * tg1;
            float h00 = og0 * tanhf(c00);
            float h01 = og1 * tanhf(c01);
            *reinterpret_cast<float2*>(out + (long)N * HID + (long)n * HID + 2 * p)
                = make_float2(h00, h01);
            *reinterpret_cast<float2*>(out + 2L * N * HID + (long)n * HID + 2 * p)
                = make_float2(c00, c01);
            r0 = fmaxf(h00, 0.0f);
            r1 = fmaxf(h01, 0.0f);
        }
        sm[nl * 64 + 2 * p]     = r0;
        sm[nl * 64 + 2 * p + 1] = r1;
    }
    // stage Wl
    {
        float4* wl4 = reinterpret_cast<float4*>(sm + 4096);
        const float4* wlg = reinterpret_cast<const float4*>(Wl);
        #pragma unroll
        for (int r = 0; r < 4; ++r) wl4[tid + r * 256] = wlg[tid + r * 256];
    }
    __syncthreads();

    // ---- out = relu(h0) @ Wl + bl ----
    float o0[8], o1[8];
    {
        float b0 = bl[2 * p], b1 = bl[2 * p + 1];
        #pragma unroll
        for (int i = 0; i < 8; ++i) { o0[i] = b0; o1[i] = b1; }
    }
    for (int k = 0; k < 64; ++k) {
        float2 w = *reinterpret_cast<const float2*>(sm + 4096 + k * 64 + 2 * p);
        #pragma unroll
        for (int i = 0; i < 8; ++i) {
            float a = sm[(ty + 8 * i) * 64 + k];
            o0[i] = fmaf(a, w.x, o0[i]);
            o1[i] = fmaf(a, w.y, o1[i]);
        }
    }
    #pragma unroll
    for (int i = 0; i < 8; ++i) {
        int n = nb + ty + 8 * i;
        if (n < N)
            *reinterpret_cast<float2*>(out + (long)n * HID + 2 * p) = make_float2(o0[i], o1[i]);
    }
}

// ---------------- launch ----------------
extern "C" void kernel_launch(void* const* d_in, const int* in_sizes, int n_in,
                              void* d_out, int out_size) {
    const float* x   = (const float*)d_in[0];
    const int*   ei  = (const int*)d_in[1];
    const float* ew  = (const float*)d_in[2];
    const float* h   = (const float*)d_in[3];
    const float* c   = (const float*)d_in[4];
    const float* Wx  = (const float*)d_in[5];
    const float* bg  = (const float*)d_in[6];
    const float* th  = (const float*)d_in[7];
    const float* cb  = (const float*)d_in[8];
    const float* Wl  = (const float*)d_in[9];
    const float* bl  = (const float*)d_in[10];
    float* out = (float*)d_out;

    const int N = in_sizes[0] / IN_DIM;
    const int E = in_sizes[1] / 2;
    const int* src = ei;
    const int* dst = ei + E;

    // CRITICAL: __device__ symbols must be resolved to device addresses on the
    // host side — passing the symbol name directly hands the kernel the HOST
    // shadow address (silently readable via ATS on GB300 -> reads zeros).
    void *p_deg, *p_lapw, *p_tx1, *p_agg2;
    cudaGetSymbolAddress(&p_deg,  g_deg);
    cudaGetSymbolAddress(&p_lapw, g_lapw);
    cudaGetSymbolAddress(&p_tx1,  g_Tx1);
    cudaGetSymbolAddress(&p_agg2, g_agg2);

    cudaMemsetAsync(p_deg,  0, (size_t)N * sizeof(float));
    cudaMemsetAsync(p_tx1,  0, (size_t)N * HID * sizeof(float));
    cudaMemsetAsync(p_agg2, 0, (size_t)N * HID * sizeof(float));

    k_deg <<<(E + 255) / 256, 256>>>(src, dst, ew, E);
    k_lapw<<<(E + 255) / 256, 256>>>(src, dst, ew, E);
    k_pack<<<(KTOT * NCOLS + 255) / 256, 256>>>(Wx, bg, th, cb);

    long st = (long)E * 16;
    unsigned sblocks = (unsigned)((st + 255) / 256);
    // Tx1 = L_hat @ h
    k_scatter<<<sblocks, 256>>>(src, dst, (const float*)p_lapw,
                                (const float4*)h, (float*)p_tx1, E);
    // agg2 = L_hat @ Tx1   (Tx2 = 2*agg2 - h folded into the GEMM loader)
    k_scatter<<<sblocks, 256>>>(src, dst, (const float*)p_lapw,
                                (const float4*)p_tx1, (float*)p_agg2, E);

    k_fused<<<(N + NPB - 1) / NPB, 256>>>(x, h, c, Wl, bl, out, N);
}

// round 3
// speedup vs baseline: 1.2868x; 1.2868x over previous
#include <cuda_runtime.h>
#include <math.h>

#define NNODES_MAX 100000
#define NEDGES_MAX 1600000
#define IN_DIM 128
#define HID 64
#define KTOT 320   // IN_DIM + 3*HID
#define NCOLS 256  // 4 gates * HID
#define NCHUNK 20  // KTOT / 16
#define NPB 64

// ---------------- scratch (static device globals; no allocation) ----------------
__device__ __align__(16) float g_deg [NNODES_MAX];
__device__ __align__(16) float g_lapw[NEDGES_MAX];
__device__ __align__(16) float g_Tx1 [NNODES_MAX * HID];
__device__ __align__(16) float g_Tx2 [NNODES_MAX * HID];   // init to -h, scatter adds 2*L@Tx1
__device__ __align__(16) float g_Wp  [KTOT * NCOLS];
__device__ __align__(16) float g_biasp[NCOLS];

// ---------------- helpers ----------------
__device__ __forceinline__ float sigf(float v) { return 1.0f / (1.0f + expf(-v)); }

__device__ __forceinline__ unsigned long long ffma2(unsigned long long a,
                                                    unsigned long long b,
                                                    unsigned long long c) {
    unsigned long long d;
    asm("fma.rn.f32x2 %0, %1, %2, %3;" : "=l"(d) : "l"(a), "l"(b), "l"(c));
    return d;
}
__device__ __forceinline__ float2 u2f(unsigned long long u) {
    float2 f; asm("mov.b64 {%0,%1}, %2;" : "=f"(f.x), "=f"(f.y) : "l"(u)); return f;
}
__device__ __forceinline__ unsigned long long dup2(float v) {
    unsigned long long r; asm("mov.b64 %0, {%1, %1};" : "=l"(r) : "f"(v)); return r;
}
__device__ __forceinline__ void cp16(void* smem, const void* gmem) {
    unsigned sa = (unsigned)__cvta_generic_to_shared(smem);
    asm volatile("cp.async.cg.shared.global [%0], [%1], 16;" :: "r"(sa), "l"(gmem));
}
#define CP_COMMIT() asm volatile("cp.async.commit_group;" ::: "memory")
#define CP_WAIT0()  asm volatile("cp.async.wait_group 0;"  ::: "memory")

// ---------------- kernel 1: degree ----------------
__global__ void k_deg(const int* __restrict__ src, const int* __restrict__ dst,
                      const float* __restrict__ ew, int E) {
    int e = blockIdx.x * blockDim.x + threadIdx.x;
    if (e >= E) return;
    int s = src[e];
    float w = (s == dst[e]) ? 0.0f : ew[e];
    if (w != 0.0f) atomicAdd(&g_deg[s], w);
}

// ---------------- kernel 2: lap_w ----------------
__global__ void k_lapw(const int* __restrict__ src, const int* __restrict__ dst,
                       const float* __restrict__ ew, int E) {
    int e = blockIdx.x * blockDim.x + threadIdx.x;
    if (e >= E) return;
    int s = src[e], d = dst[e];
    float w  = (s == d) ? 0.0f : ew[e];
    float ds = g_deg[s], dd = g_deg[d];
    float is = (ds > 0.0f) ? rsqrtf(ds) : 0.0f;
    float id = (dd > 0.0f) ? rsqrtf(dd) : 0.0f;
    g_lapw[e] = -is * w * id;
}

// ---------------- kernel 3: pack weights [320][256] + fused bias ----------------
__global__ void k_pack(const float* __restrict__ Wx, const float* __restrict__ bg,
                       const float* __restrict__ theta, const float* __restrict__ convb) {
    int idx = blockIdx.x * blockDim.x + threadIdx.x;
    if (idx >= KTOT * NCOLS) return;
    int k = idx / NCOLS, j = idx % NCOLS;
    int g = j >> 6, o = j & 63;
    float v;
    if (k < IN_DIM) {
        v = Wx[(g * IN_DIM + k) * HID + o];
    } else {
        int kk = k - IN_DIM;
        int cheb = kk / HID, r = kk % HID;
        v = theta[((g * 3 + cheb) * HID + r) * HID + o];
    }
    g_Wp[idx] = v;
    if (idx < NCOLS) g_biasp[idx] = bg[idx] + convb[idx];
}

// ---------------- kernel 3b: init Tx2 buffer to -h ----------------
__global__ void k_initneg(const float4* __restrict__ h, float4* __restrict__ o, int n4) {
    int i = blockIdx.x * blockDim.x + threadIdx.x;
    if (i >= n4) return;
    float4 v = h[i];
    o[i] = make_float4(-v.x, -v.y, -v.z, -v.w);
}

// ---------------- kernel 4: scatter  zout[dst] += scale * lap_w * zin[src] ----------------
__global__ void k_scatter(const int* __restrict__ src, const int* __restrict__ dst,
                          const float* __restrict__ lapw, float scale,
                          const float4* __restrict__ zin, float* __restrict__ zout, int E) {
    long idx = (long)blockIdx.x * blockDim.x + threadIdx.x;
    int e = (int)(idx >> 4);
    if (e >= E) return;
    int c = (int)(idx & 15);
    float lw = lapw[e] * scale;
    if (lw == 0.0f) return;
    int s = src[e], d = dst[e];
    float4 v = zin[s * 16 + c];
    float* p = zout + ((long)d * 64 + c * 4);
    asm volatile("red.global.add.v4.f32 [%0], {%1,%2,%3,%4};"
                 :: "l"(p), "f"(lw * v.x), "f"(lw * v.y), "f"(lw * v.z), "f"(lw * v.w)
                 : "memory");
}

// ---------------- kernel 5: pipelined fused GEMM + LSTM gates + relu@Wl ----------------
// 256 threads, 64 nodes/CTA. Thread tile: 8 nodes x 4 gates x hid-pair (f32x2 accs).
// Double-buffered: W tile via cp.async.cg, X tile via register prefetch.
__global__ __launch_bounds__(256, 2) void k_fused(
    const float* __restrict__ x, const float* __restrict__ h,
    const float* __restrict__ tx1, const float* __restrict__ tx2,
    const float* __restrict__ c, const float* __restrict__ Wl,
    const float* __restrict__ bl, float* __restrict__ out, int N) {

    __shared__ __align__(16) float Xs[2][NPB * 16];   // [buf][node][16]   2x4KB
    __shared__ __align__(16) float Ws[2][16 * NCOLS]; // [buf][kk][256]    2x16KB

    const int tid = threadIdx.x;
    const int p  = tid & 31;
    const int ty = tid >> 5;
    const int nb = blockIdx.x * NPB;

    // X prefetch mapping: thread -> (node xn, quad xq)
    const int xn = tid >> 2;
    const int xq = tid & 3;
    const int gxn = nb + xn;

    unsigned long long acc[8][4];
    {
        unsigned long long bini[4];
        #pragma unroll
        for (int g = 0; g < 4; ++g)
            bini[g] = *reinterpret_cast<const unsigned long long*>(&g_biasp[g * 64 + 2 * p]);
        #pragma unroll
        for (int i = 0; i < 8; ++i)
            #pragma unroll
            for (int g = 0; g < 4; ++g) acc[i][g] = bini[g];
    }

    // source of X tile for chunk kc
    auto load_x = [&](int kc) -> float4 {
        const float* sp; int ld, col;
        if (kc < 8)       { sp = x;   ld = IN_DIM; col = kc * 16; }
        else if (kc < 12) { sp = h;   ld = HID;    col = (kc - 8)  * 16; }
        else if (kc < 16) { sp = tx1; ld = HID;    col = (kc - 12) * 16; }
        else              { sp = tx2; ld = HID;    col = (kc - 16) * 16; }
        if (gxn < N)
            return *reinterpret_cast<const float4*>(sp + (long)gxn * ld + col + xq * 4);
        return make_float4(0.f, 0.f, 0.f, 0.f);
    };
    auto issue_w = [&](int kc, int buf) {
        const float4* wp4 = reinterpret_cast<const float4*>(g_Wp + kc * 16 * NCOLS);
        float4* ws4 = reinterpret_cast<float4*>(Ws[buf]);
        #pragma unroll
        for (int r = 0; r < 4; ++r)
            cp16(&ws4[tid + r * 256], &wp4[tid + r * 256]);
        CP_COMMIT();
    };

    // prologue: tile 0
    issue_w(0, 0);
    {
        float4 v = load_x(0);
        *reinterpret_cast<float4*>(&Xs[0][xn * 16 + xq * 4]) = v;
    }
    CP_WAIT0();
    __syncthreads();

    for (int kc = 0; kc < NCHUNK; ++kc) {
        const int cur = kc & 1;
        float4 xv;
        if (kc < NCHUNK - 1) {
            issue_w(kc + 1, cur ^ 1);   // safe: prior readers of buf cur^1 synced at end of kc-1
            xv = load_x(kc + 1);
        }
        // ---- compute on buffer cur ----
        {
            const unsigned long long* wr =
                reinterpret_cast<const unsigned long long*>(Ws[cur]);
            const float* xf = Xs[cur];
            #pragma unroll
            for (int kk = 0; kk < 16; ++kk) {
                unsigned long long a[8], b[4];
                #pragma unroll
                for (int i = 0; i < 8; ++i) a[i] = dup2(xf[(ty + 8 * i) * 16 + kk]);
                #pragma unroll
                for (int g = 0; g < 4; ++g) b[g] = wr[kk * 128 + g * 32 + p];
                #pragma unroll
                for (int i = 0; i < 8; ++i)
                    #pragma unroll
                    for (int g = 0; g < 4; ++g) acc[i][g] = ffma2(a[i], b[g], acc[i][g]);
            }
        }
        if (kc < NCHUNK - 1)
            *reinterpret_cast<float4*>(&Xs[cur ^ 1][xn * 16 + xq * 4]) = xv;
        CP_WAIT0();
        __syncthreads();
    }

    // ---- phase 2: gates + h0/c0 + relu(h0)@Wl + bl (reuse Ws as smem) ----
    float* Hs  = Ws[0];   // [64][64] relu(h0)
    float* Wls = Ws[1];   // [64][64]

    #pragma unroll
    for (int i = 0; i < 8; ++i) {
        int nl = ty + 8 * i;
        int n = nb + nl;
        float2 pi = u2f(acc[i][0]);
        float2 pf = u2f(acc[i][1]);
        float2 pt = u2f(acc[i][2]);
        float2 po = u2f(acc[i][3]);
        float r0 = 0.0f, r1 = 0.0f;
        if (n < N) {
            float2 cold = *reinterpret_cast<const float2*>(c + (long)n * HID + 2 * p);
            float ig0 = sigf(pi.x), ig1 = sigf(pi.y);
            float fg0 = sigf(pf.x), fg1 = sigf(pf.y);
            float tg0 = tanhf(pt.x), tg1 = tanhf(pt.y);
            float og0 = sigf(po.x), og1 = sigf(po.y);
            float c00 = fg0 * cold.x + ig0 * tg0;
            float c01 = fg1 * cold.y + ig1 * tg1;
            float h00 = og0 * tanhf(c00);
            float h01 = og1 * tanhf(c01);
            *reinterpret_cast<float2*>(out + (long)N * HID + (long)n * HID + 2 * p)
                = make_float2(h00, h01);
            *reinterpret_cast<float2*>(out + 2L * N * HID + (long)n * HID + 2 * p)
                = make_float2(c00, c01);
            r0 = fmaxf(h00, 0.0f);
            r1 = fmaxf(h01, 0.0f);
        }
        Hs[nl * 64 + 2 * p]     = r0;
        Hs[nl * 64 + 2 * p + 1] = r1;
    }
    {
        float4* wl4 = reinterpret_cast<float4*>(Wls);
        const float4* wlg = reinterpret_cast<const float4*>(Wl);
        #pragma unroll
        for (int r = 0; r < 4; ++r) wl4[tid + r * 256] = wlg[tid + r * 256];
    }
    __syncthreads();

    float o0[8], o1[8];
    {
        float b0 = bl[2 * p], b1 = bl[2 * p + 1];
        #pragma unroll
        for (int i = 0; i < 8; ++i) { o0[i] = b0; o1[i] = b1; }
    }
    for (int k = 0; k < 64; ++k) {
        float2 w = *reinterpret_cast<const float2*>(Wls + k * 64 + 2 * p);
        #pragma unroll
        for (int i = 0; i < 8; ++i) {
            float a = Hs[(ty + 8 * i) * 64 + k];
            o0[i] = fmaf(a, w.x, o0[i]);
            o1[i] = fmaf(a, w.y, o1[i]);
        }
    }
    #pragma unroll
    for (int i = 0; i < 8; ++i) {
        int n = nb + ty + 8 * i;
        if (n < N)
            *reinterpret_cast<float2*>(out + (long)n * HID + 2 * p) = make_float2(o0[i], o1[i]);
    }
}

// ---------------- launch ----------------
extern "C" void kernel_launch(void* const* d_in, const int* in_sizes, int n_in,
                              void* d_out, int out_size) {
    const float* x   = (const float*)d_in[0];
    const int*   ei  = (const int*)d_in[1];
    const float* ew  = (const float*)d_in[2];
    const float* h   = (const float*)d_in[3];
    const float* c   = (const float*)d_in[4];
    const float* Wx  = (const float*)d_in[5];
    const float* bg  = (const float*)d_in[6];
    const float* th  = (const float*)d_in[7];
    const float* cb  = (const float*)d_in[8];
    const float* Wl  = (const float*)d_in[9];
    const float* bl  = (const float*)d_in[10];
    float* out = (float*)d_out;

    const int N = in_sizes[0] / IN_DIM;
    const int E = in_sizes[1] / 2;
    const int* src = ei;
    const int* dst = ei + E;

    // __device__ symbols must be resolved to device addresses on the host side.
    void *p_deg, *p_lapw, *p_tx1, *p_tx2;
    cudaGetSymbolAddress(&p_deg,  g_deg);
    cudaGetSymbolAddress(&p_lapw, g_lapw);
    cudaGetSymbolAddress(&p_tx1,  g_Tx1);
    cudaGetSymbolAddress(&p_tx2,  g_Tx2);

    cudaMemsetAsync(p_deg, 0, (size_t)N * sizeof(float));
    cudaMemsetAsync(p_tx1, 0, (size_t)N * HID * sizeof(float));

    int n4 = N * HID / 4;
    k_initneg<<<(n4 + 255) / 256, 256>>>((const float4*)h, (float4*)p_tx2, n4);

    k_deg <<<(E + 255) / 256, 256>>>(src, dst, ew, E);
    k_lapw<<<(E + 255) / 256, 256>>>(src, dst, ew, E);
    k_pack<<<(KTOT * NCOLS + 255) / 256, 256>>>(Wx, bg, th, cb);

    long st = (long)E * 16;
    unsigned sblocks = (unsigned)((st + 255) / 256);
    // Tx1 = L_hat @ h
    k_scatter<<<sblocks, 256>>>(src, dst, (const float*)p_lapw, 1.0f,
                                (const float4*)h, (float*)p_tx1, E);
    // Tx2 = 2 * L_hat @ Tx1 - h   (buffer pre-initialized to -h)
    k_scatter<<<sblocks, 256>>>(src, dst, (const float*)p_lapw, 2.0f,
                                (const float4*)p_tx1, (float*)p_tx2, E);

    k_fused<<<(N + NPB - 1) / NPB, 256>>>(x, h, (const float*)p_tx1,
                                          (const float*)p_tx2, c, Wl, bl, out, N);
}